// round 11
// baseline (speedup 1.0000x reference)
#include <cuda_runtime.h>

#define CC   10
#define DD   11
#define FULL 0xFFFFFFFFu

__device__ __forceinline__ float rsum16(float v) {
    #pragma unroll
    for (int o = 1; o < 16; o <<= 1) v += __shfl_xor_sync(FULL, v, o);
    return v;
}

__global__ __launch_bounds__(64) void pve_kernel(
    const float* __restrict__ x,      // [2,10,30,30] one-hot
    const float* __restrict__ w_in,   // [33,11]
    const float* __restrict__ w_out,  // [11,11]
    const float* __restrict__ w_ff1,  // [1,11]
    const float* __restrict__ w_ff2,  // [11,1]
    const float* __restrict__ ln1_g,  // [11]
    const float* __restrict__ ln2_g,  // [11]
    float* __restrict__ out)          // [1800,10,100]
{
    __shared__ float              tile[1000];   // output-layout [c][10][10]
    __shared__ unsigned long long hredA[2], hredB[2];

    const int tid  = threadIdx.x;               // 0..63
    const int lane = tid & 31;
    const int wrp  = tid >> 5;
    const int b    = blockIdx.x;                // pixel id 0..1799
    const int n    = b / 900;
    const int rem  = b % 900;
    const int pi   = rem / 30, pj = rem % 30;

    const bool haspad = (pi < 4) | (pi > 25) | (pj < 4) | (pj > 25);
    const float* xn = x + n * 9000;

    // ── hoist weight loads (border, warp 0) to overlap staging ──
    const int d = lane;
    float kk[DD], vv[DD], wo[DD];
    float q10 = 0.f, g1 = 0.f, g2 = 0.f, f1 = 0.f, f2 = 0.f;
    if (haspad && wrp == 0 && d < DD) {
        q10 = w_in[d * DD + 10];
        g1  = ln1_g[d];
        g2  = ln2_g[d];
        f1  = w_ff1[d];
        f2  = w_ff2[d];
        #pragma unroll
        for (int c = 0; c < DD; c++) {
            kk[c] = w_in[(DD + d) * DD + c];
            vv[c] = w_in[(2 * DD + d) * DD + c];
            wo[c] = w_out[d * DD + c];
        }
    }

    // ── zero the masked stripes (l%10==9 or l>=90): 190 floats, disjoint
    //    from staged slots ──
    #pragma unroll
    for (int pass = 0; pass < 3; pass++) {
        int k = tid + 64 * pass;
        if (k < 190) {
            int c = k / 19, i = k - 19 * c;
            int l = (i < 9) ? (10 * i + 9) : (90 + (i - 9));
            tile[c * 100 + l] = 0.f;
        }
    }

    // ── stage the x window into output layout; fuse histogram (border) ──
    // slot s < 81: (row,col) in 9x9; thread t owns s = t and s = t+64.
    unsigned long long cA = 0ull, cB = 0ull;   // classes 0..5 / 6..9
    #pragma unroll
    for (int pass = 0; pass < 2; pass++) {
        int s = tid + 64 * pass;
        if (s < 81) {
            int row = s / 9, col = s - 9 * row;
            int si = pi - 4 + row, sj = pj - 4 + col;
            bool inimg = ((unsigned)si < 30u) & ((unsigned)sj < 30u);
            const float* gp = xn + si * 30 + sj;  // deref only if inimg
            float* sp = tile + row * 10 + col;
            #pragma unroll 2
            for (int c = 0; c < CC; c++) {
                float val = inimg ? gp[c * 900] : 0.f;
                sp[c * 100] = val;
                if (haspad && val > 0.5f) {
                    if (c < 6) cA += 1ull << (8 * c);
                    else       cB += 1ull << (8 * (c - 6));
                }
            }
        }
    }

    // per-warp histogram reduce -> smem (border only)
    if (haspad) {
        #pragma unroll
        for (int o = 1; o < 32; o <<= 1) {
            cA += __shfl_xor_sync(FULL, cA, o);
            cB += __shfl_xor_sync(FULL, cB, o);
        }
        if (lane == 0) { hredA[wrp] = cA; hredB[wrp] = cB; }
    }
    __syncthreads();

    // ── border pipeline + OOB fixup, warp 0 only ──
    if (haspad) {
        if (wrp == 0) {
            unsigned long long tA = hredA[0] + hredA[1];
            unsigned long long tB = hredB[0] + hredB[1];
            int r0 = max(0, 4 - pi), r1 = min(8, 33 - pi);
            int c0 = max(0, 4 - pj), c1 = min(8, 33 - pj);
            int nIn = (r1 - r0 + 1) * (c1 - c0 + 1);
            float hf[DD];
            #pragma unroll
            for (int c = 0; c < 6; c++)  hf[c] = (float)((tA >> (8 * c)) & 0xFFull);
            #pragma unroll
            for (int c = 6; c < 10; c++) hf[c] = (float)((tB >> (8 * (c - 6))) & 0xFFull);
            hf[10] = (float)(81 - nIn);

            // attention for the padding-class query; lane d owns dim d
            float num = 0.f, den = 0.f;
            if (d < DD) {
                #pragma unroll
                for (int c = 0; c < DD; c++) {
                    float e = __expf(q10 * kk[c]) * hf[c];
                    den += e;
                    num += e * vv[c];
                }
            }
            float ao = (d < DD) ? num / den : 0.f;

            // svec = e_10 + ao @ w_out^T
            float acc = (d == 10) ? 1.f : 0.f;
            #pragma unroll
            for (int c = 0; c < DD; c++) {
                float a = __shfl_sync(FULL, ao, c);
                if (d < DD) acc += a * wo[c];
            }
            float sv = (d < DD) ? acc : 0.f;

            // LN1
            float s1 = rsum16(sv);
            float s2 = rsum16(sv * sv);
            float m   = s1 * (1.f / 11.f);
            float var = fmaxf(s2 * (1.f / 11.f) - m * m, 0.f);
            float inv = rsqrtf(var + 1e-5f);
            float h1  = (d < DD) ? (sv - m) * inv * g1 : 0.f;

            // FF
            float tt = rsum16(h1 * f1);
            tt = fmaxf(tt, 0.f);
            float h2 = (d < DD) ? h1 + tt * f2 : 0.f;

            // LN2
            float t1 = rsum16(h2);
            float t2 = rsum16(h2 * h2);
            float m2   = t1 * (1.f / 11.f);
            float var2 = fmaxf(t2 * (1.f / 11.f) - m2 * m2, 0.f);
            float inv2 = rsqrtf(var2 + 1e-5f);
            float hhv  = (d < DD) ? (h2 - m2) * inv2 * g2 : 0.f;

            // softmax over classes 0..9 (post-LN values bounded: no max-sub)
            float ex = (d < CC) ? __expf(hhv) : 0.f;
            float se = rsum16(ex);
            float pvc = ex / se;               // lane c holds padvec[c], c<10

            // broadcast padvec to all lanes
            float pv[CC];
            #pragma unroll
            for (int c = 0; c < CC; c++) pv[c] = __shfl_sync(FULL, pvc, c);

            // fixup: OOB in-window slots get padvec[c]
            #pragma unroll
            for (int pass = 0; pass < 3; pass++) {
                int s = lane + 32 * pass;
                if (s < 81) {
                    int row = s / 9, col = s - 9 * row;
                    int si = pi - 4 + row, sj = pj - 4 + col;
                    if (!(((unsigned)si < 30u) & ((unsigned)sj < 30u))) {
                        float* sp = tile + row * 10 + col;
                        #pragma unroll
                        for (int c = 0; c < CC; c++) sp[c * 100] = pv[c];
                    }
                }
            }
        }
        __syncthreads();   // uniform per block: legal
    }

    // ── scatter: pure aligned copy, 250 float4 ──
    float4*       o4 = reinterpret_cast<float4*>(out + (long)b * 1000);
    const float4* t4 = reinterpret_cast<const float4*>(tile);
    #pragma unroll
    for (int i = 0; i < 4; i++) {
        int q = tid + 64 * i;
        if (q < 250) o4[q] = t4[q];
    }
}

extern "C" void kernel_launch(void* const* d_in, const int* in_sizes, int n_in,
                              void* d_out, int out_size) {
    const float* x     = (const float*)d_in[0];
    const float* w_in  = (const float*)d_in[1];
    const float* w_out = (const float*)d_in[2];
    const float* w_ff1 = (const float*)d_in[3];
    const float* w_ff2 = (const float*)d_in[4];
    const float* ln1_g = (const float*)d_in[5];
    const float* ln2_g = (const float*)d_in[6];

    pve_kernel<<<1800, 64>>>(x, w_in, w_out, w_ff1, w_ff2, ln1_g, ln2_g,
                             (float*)d_out);
}